// round 3
// baseline (speedup 1.0000x reference)
#include <cuda_runtime.h>

// Problem shape (dataset-fixed): B=32, N=64, L=128, D=256, NB=2048, MAX_LEN=8192.
// Sizes derived at launch; static scratch sized with headroom.

#define T_CHUNK 256          // t-positions per block (== blockDim)

// Static device scratch (allocation-free rule). g_cnt must be zero at launch
// entry; the last block of each batch row resets it (graph-replay safe).
__device__ float g_partial[1048576];   // B * nchunks * D partials
__device__ int   g_cnt[128];           // per-batch arrival counters (zero-init)

__global__ void __launch_bounds__(256)
k_all(const float* __restrict__ lengths_i,     // reuse name: [NB] int
      const float4* __restrict__ mb,
      float4* __restrict__ mb_out,
      const float* __restrict__ src,
      const int* __restrict__ recover,
      float* __restrict__ src_out,
      float* __restrict__ hid_out,
      float* __restrict__ len_out,
      const int* __restrict__ lengths,
      int B, int N, int NB, int Dv, int MAX_LEN, int nchunks)
{
    __shared__ int   soff[1056];       // N+1 exclusive offsets + total
    __shared__ int   stok[T_CHUNK];    // token index per t in chunk (-1 = pad)
    __shared__ float4 sred[256];

    int b     = blockIdx.y;
    int chunk = blockIdx.x;
    int t0    = chunk * T_CHUNK;
    int tid   = threadIdx.x;

    // ---- Phase 0: per-block scan of this batch row's lengths (N <= 1024) ----
    if (tid < N) soff[tid + 1] = lengths[b * N + tid];
    if (tid == 0) soff[0] = 0;
    __syncthreads();
    // Hillis-Steele inclusive scan over soff[1..N]
    for (int st = 1; st < N; st <<= 1) {
        int v = 0;
        if (tid < N && tid >= st) v = soff[tid + 1 - st];
        __syncthreads();
        if (tid < N) soff[tid + 1] += v;
        __syncthreads();
    }
    int total = soff[N];

    if (chunk == 0 && tid == 0) len_out[b] = (float)total;

    // ---- Phase 1: resolve each t in chunk -> token index; write src_out ----
    {
        int t = t0 + tid;
        int tok = -1;
        float sval = 1.0f;
        if (t < total) {
            int lo = 0, hi = N - 1;                // largest n: soff[n] <= t
            while (lo < hi) {
                int mid = (lo + hi + 1) >> 1;
                if (soff[mid] <= t) lo = mid; else hi = mid - 1;
            }
            int p = t - soff[lo];
            tok  = p * NB + b * N + lo;
            sval = src[p * NB + recover[b * N + lo]];
        }
        stok[tid] = tok;
        src_out[t * B + b] = sval;
    }
    __syncthreads();

    // ---- Phase 2: main stream. d4 lane over D, ts = t-subgroup of 4 ----
    int d4 = tid & 63;
    int ts = tid >> 6;

    float4 acc = make_float4(0.f, 0.f, 0.f, 0.f);

    #pragma unroll 8
    for (int tt = ts; tt < T_CHUNK; tt += 4) {
        int tok = stok[tt];                       // broadcast, no gmem dep
        float4 v = make_float4(0.f, 0.f, 0.f, 0.f);
        if (tok >= 0)
            v = __ldcs(&mb[(long)tok * Dv + d4]);
        __stcs(&mb_out[((long)((t0 + tt) * B + b)) * Dv + d4], v);
        acc.x += v.x; acc.y += v.y; acc.z += v.z; acc.w += v.w;
    }

    // ---- Phase 3: deterministic block reduction -> partial ----
    sred[tid] = acc;
    __syncthreads();
    if (ts == 0) {
        float4 a0 = sred[d4];
        float4 a1 = sred[64  + d4];
        float4 a2 = sred[128 + d4];
        float4 a3 = sred[192 + d4];
        float4 tot;
        tot.x = (a0.x + a1.x) + (a2.x + a3.x);
        tot.y = (a0.y + a1.y) + (a2.y + a3.y);
        tot.z = (a0.z + a1.z) + (a2.z + a3.z);
        tot.w = (a0.w + a1.w) + (a2.w + a3.w);
        float4* pp = (float4*)g_partial;
        pp[(long)(b * nchunks + chunk) * Dv + d4] = tot;
    }

    // ---- Phase 4: last block of this batch row reduces encoder hidden ----
    __shared__ int s_last;
    __threadfence();                               // publish partials
    __syncthreads();                               // all threads' work done
    if (tid == 0) {
        int old = atomicAdd(&g_cnt[b], 1);
        s_last = (old == nchunks - 1);
    }
    __syncthreads();
    if (s_last) {
        __threadfence();                           // acquire others' partials
        int D = Dv * 4;
        float inv = 1.0f / (float)total;
        for (int d = tid; d < D; d += blockDim.x) {
            const float* p = g_partial + (long)(b * nchunks) * D + d;
            float s = 0.f;
            #pragma unroll 8
            for (int c = 0; c < nchunks; c++)
                s += p[(long)c * D];
            hid_out[b * D + d] = s * inv;
        }
        if (tid == 0) g_cnt[b] = 0;                // reset for next replay
    }
}

// ---------------------------------------------------------------------------
extern "C" void kernel_launch(void* const* d_in, const int* in_sizes, int n_in,
                              void* d_out, int out_size)
{
    const float* src     = (const float*)d_in[0];   // [L, NB, 1]
    const float* mb      = (const float*)d_in[1];   // [L, NB, D]
    const int*   lengths = (const int*)  d_in[2];   // [NB]
    const int*   recover = (const int*)  d_in[3];   // [NB]

    int NB = in_sizes[2];
    int L  = in_sizes[0] / NB;
    int D  = in_sizes[1] / in_sizes[0];

    // out_size = NB*L*(1+D) + B*(D+1)  ->  solve for B.
    long rem = (long)out_size - (long)NB * L * (1 + D);
    int B = (int)(rem / (D + 1));
    int N = NB / B;
    int MAX_LEN = N * L;

    float* out      = (float*)d_out;
    float* src_out  = out;                                   // [MAX_LEN, B, 1]
    float* mb_out   = out + (long)MAX_LEN * B;               // [MAX_LEN, B, D]
    float* hid_out  = mb_out + (long)MAX_LEN * B * D;        // [1, B, D]
    float* len_out  = hid_out + (long)B * D;                 // [B]

    int nchunks = MAX_LEN / T_CHUNK;
    dim3 grid(nchunks, B);
    k_all<<<grid, 256>>>(nullptr,
                         (const float4*)mb, (float4*)mb_out,
                         src, recover, src_out, hid_out, len_out,
                         lengths, B, N, NB, D / 4, MAX_LEN, nchunks);
}